// round 1
// baseline (speedup 1.0000x reference)
#include <cuda_runtime.h>
#include <math.h>

// Problem constants
#define NPTS 4096
#define DDIM 2048
#define NCLS 128
#define MROWS 256      // stacked [meanR; meanT]
#define KSPLIT 16      // K-split factor for the Gram GEMM
#define MARGIN 0.5f

// ---------------- scratch (static device globals; no allocation) ----------------
__device__ float d_sum[2][NCLS][DDIM];          // class sums, R and T    (2 MB)
__device__ int   d_cnt[NCLS];                   // class counts
__device__ float d_M[MROWS][DDIM];              // stacked class means    (2 MB)
__device__ float d_Spart[KSPLIT][MROWS*MROWS];  // GEMM partials          (4 MB)
__device__ float d_S[MROWS*MROWS];              // reduced Gram matrix    (256 KB)

// =====================================================================
// Kernel 1: deterministic per-class segment sums.
// grid (NCLS, 4 D-chunks of 512), 128 threads. Each block builds the
// list of rows belonging to its class (prefix-sum compaction -> fixed,
// deterministic order), then streams those rows' column chunk.
// =====================================================================
__global__ void seg_sum_kernel(const float* __restrict__ m1,
                               const float* __restrict__ m2,
                               const int* __restrict__ tgt) {
    const int c     = blockIdx.x;
    const int chunk = blockIdx.y;        // 0..3
    const int tid   = threadIdx.x;       // 128 threads

    __shared__ int s_tgt[NPTS];          // 16 KB
    __shared__ int s_rows[NPTS];         // 16 KB (robust worst-case capacity)
    __shared__ int s_pref[128];

    // stage targets
    for (int i = tid; i < NPTS; i += 128) s_tgt[i] = tgt[i];
    __syncthreads();

    // per-thread count of matches in its strided slice
    int cl = 0;
    #pragma unroll 8
    for (int i = tid; i < NPTS; i += 128) cl += (s_tgt[i] == c);
    s_pref[tid] = cl;
    __syncthreads();

    // Hillis-Steele inclusive scan over 128 threads
    #pragma unroll
    for (int off = 1; off < 128; off <<= 1) {
        int v   = s_pref[tid];
        int add = (tid >= off) ? s_pref[tid - off] : 0;
        __syncthreads();
        s_pref[tid] = v + add;
        __syncthreads();
    }
    const int mtot = s_pref[127];
    int woff = s_pref[tid] - cl;   // exclusive offset (deterministic order)

    for (int i = tid; i < NPTS; i += 128)
        if (s_tgt[i] == c) s_rows[woff++] = i;
    __syncthreads();

    if (tid == 0 && chunk == 0) d_cnt[c] = mtot;

    const int col = chunk * 512 + tid * 4;
    float4 aR = make_float4(0.f, 0.f, 0.f, 0.f);
    float4 aT = make_float4(0.f, 0.f, 0.f, 0.f);
    #pragma unroll 4
    for (int j = 0; j < mtot; j++) {
        size_t base = (size_t)s_rows[j] * DDIM + col;
        float4 x = *(const float4*)(m1 + base);
        float4 y = *(const float4*)(m2 + base);
        aR.x += x.x; aR.y += x.y; aR.z += x.z; aR.w += x.w;
        aT.x += y.x; aT.y += y.y; aT.z += y.z; aT.w += y.w;
    }
    *(float4*)&d_sum[0][c][col] = aR;
    *(float4*)&d_sum[1][c][col] = aT;
}

// =====================================================================
// Kernel 2: means. grid 256 blocks (one per M row), 256 threads.
// =====================================================================
__global__ void means_kernel() {
    const int row = blockIdx.x;           // 0..255
    const int c   = row & (NCLS - 1);
    const float inv = 1.0f / fmaxf((float)d_cnt[c], 1.0f);
    const float* src = &d_sum[row >> 7][c][0];
    for (int col = threadIdx.x * 4; col < DDIM; col += blockDim.x * 4) {
        float4 v = *(const float4*)(src + col);
        v.x *= inv; v.y *= inv; v.z *= inv; v.w *= inv;
        *(float4*)&d_M[row][col] = v;
    }
}

// =====================================================================
// Kernel 3: S_part[z] = M[:, zK:(z+1)K] * M[:, zK:(z+1)K]^T
// grid (4,4,KSPLIT), 256 threads (16x16), 64x64 tile, 4x4 micro-tile.
// K-major smem tiles -> conflict-free float4 LDS; FFMA-bound by design.
// =====================================================================
__global__ void gemm_kernel() {
    const int tid = threadIdx.x;
    const int tx = tid & 15, ty = tid >> 4;
    const int row0 = blockIdx.x * 64;
    const int col0 = blockIdx.y * 64;
    const int kb0  = blockIdx.z * (DDIM / KSPLIT);   // 128-wide K slice

    __shared__ float As[64][64];   // [k][row], 16 KB
    __shared__ float Bs[64][64];   // [k][col], 16 KB

    float acc[4][4];
    #pragma unroll
    for (int i = 0; i < 4; i++)
        #pragma unroll
        for (int j = 0; j < 4; j++) acc[i][j] = 0.f;

    #pragma unroll
    for (int half = 0; half < 2; half++) {
        const int kbase = kb0 + half * 64;
        // cooperative transposed load: lane varies over row -> conflict-free STS
        #pragma unroll
        for (int it = 0; it < 4; it++) {
            int t = tid + it * 256;        // 0..1023
            int r = t & 63;                // tile row
            int q = t >> 6;                // float4 index in k (0..15)
            float4 a = *(const float4*)&d_M[row0 + r][kbase + q * 4];
            As[q*4+0][r] = a.x; As[q*4+1][r] = a.y;
            As[q*4+2][r] = a.z; As[q*4+3][r] = a.w;
            float4 b = *(const float4*)&d_M[col0 + r][kbase + q * 4];
            Bs[q*4+0][r] = b.x; Bs[q*4+1][r] = b.y;
            Bs[q*4+2][r] = b.z; Bs[q*4+3][r] = b.w;
        }
        __syncthreads();
        #pragma unroll 16
        for (int k = 0; k < 64; k++) {
            float4 av = *(const float4*)&As[k][ty * 4];
            float4 bv = *(const float4*)&Bs[k][tx * 4];
            acc[0][0] += av.x * bv.x; acc[0][1] += av.x * bv.y;
            acc[0][2] += av.x * bv.z; acc[0][3] += av.x * bv.w;
            acc[1][0] += av.y * bv.x; acc[1][1] += av.y * bv.y;
            acc[1][2] += av.y * bv.z; acc[1][3] += av.y * bv.w;
            acc[2][0] += av.z * bv.x; acc[2][1] += av.z * bv.y;
            acc[2][2] += av.z * bv.z; acc[2][3] += av.z * bv.w;
            acc[3][0] += av.w * bv.x; acc[3][1] += av.w * bv.y;
            acc[3][2] += av.w * bv.z; acc[3][3] += av.w * bv.w;
        }
        __syncthreads();
    }

    float* out = d_Spart[blockIdx.z];
    #pragma unroll
    for (int i = 0; i < 4; i++)
        #pragma unroll
        for (int j = 0; j < 4; j++)
            out[(size_t)(row0 + ty*4 + i) * MROWS + (col0 + tx*4 + j)] = acc[i][j];
}

// =====================================================================
// Kernel 4: deterministic K-split reduction. grid 256 x 256 threads.
// =====================================================================
__global__ void reduce_kernel() {
    const int idx = blockIdx.x * blockDim.x + threadIdx.x;  // 0..65535
    float s = 0.f;
    #pragma unroll
    for (int z = 0; z < KSPLIT; z++) s += d_Spart[z][idx];
    d_S[idx] = s;
}

// =====================================================================
// Kernel 5: class-pair loss reduction. 1 block, 256 threads.
// =====================================================================
__global__ void loss_kernel(float* __restrict__ out) {
    __shared__ float ra2[NCLS], ta2[NCLS], cb2[NCLS], cw[NCLS];
    const int tid = threadIdx.x;
    if (tid < NCLS) {
        int a = tid;
        float rr = d_S[a * MROWS + a];
        float tt = d_S[(NCLS + a) * MROWS + (NCLS + a)];
        float rt = d_S[a * MROWS + (NCLS + a)];
        ra2[a] = rr;
        ta2[a] = tt;
        cb2[a] = 0.25f * (rr + 2.f * rt + tt);
        cw[a]  = (float)d_cnt[a];
    }
    __syncthreads();

    double acc = 0.0;
    for (int p = tid; p < NCLS * NCLS; p += 256) {
        int a = p >> 7, b = p & (NCLS - 1);
        float g1 = 0.5f * (d_S[a * MROWS + b] + d_S[a * MROWS + (NCLS + b)]);
        float g2 = 0.5f * (d_S[(NCLS + a) * MROWS + b] +
                           d_S[(NCLS + a) * MROWS + (NCLS + b)]);
        float sq1 = fmaxf(ra2[a] + cb2[b] - 2.f * g1, 1e-12f);
        float sq2 = fmaxf(ta2[a] + cb2[b] - 2.f * g2, 1e-12f);
        float term;
        if (a == b) {
            // label=1: d2*d2 = dist^2 = clamped squared distance
            term = sq1 + sq2;
        } else {
            // label=0: relu(margin - sqrt(sqrt(sq)+1e-10))^2
            float dd1 = sqrtf(sqrtf(sq1) + 1e-10f);
            float dd2 = sqrtf(sqrtf(sq2) + 1e-10f);
            float h1 = fmaxf(MARGIN - dd1, 0.f);
            float h2 = fmaxf(MARGIN - dd2, 0.f);
            term = h1 * h1 + h2 * h2;
        }
        acc += (double)(cw[a] * cw[b] * term);
    }

    __shared__ double sred[256];
    sred[tid] = acc;
    __syncthreads();
    for (int s = 128; s > 0; s >>= 1) {
        if (tid < s) sred[tid] += sred[tid + s];
        __syncthreads();
    }
    if (tid == 0)
        out[0] = (float)(sred[0] / ((double)NPTS * (double)NPTS));
}

// =====================================================================
// kernel_launch: graph-capturable, allocation-free pipeline.
// inputs: [0] modal1 (N*D f32), [1] modal2 (N*D f32), [2] targets (N i32)
// output: scalar f32
// =====================================================================
extern "C" void kernel_launch(void* const* d_in, const int* in_sizes, int n_in,
                              void* d_out, int out_size) {
    (void)in_sizes; (void)n_in; (void)out_size;
    const float* m1  = (const float*)d_in[0];
    const float* m2  = (const float*)d_in[1];
    const int*   tgt = (const int*)d_in[2];
    float* out = (float*)d_out;

    seg_sum_kernel<<<dim3(NCLS, 4), 128>>>(m1, m2, tgt);
    means_kernel<<<MROWS, 256>>>();
    gemm_kernel<<<dim3(4, 4, KSPLIT), 256>>>();
    reduce_kernel<<<MROWS, 256>>>();
    loss_kernel<<<1, 256>>>(out);
}

// round 3
// speedup vs baseline: 1.5560x; 1.5560x over previous
#include <cuda_runtime.h>
#include <math.h>

// Problem constants
#define NPTS 4096
#define DDIM 2048
#define NCLS 128
#define MROWS 256              // stacked [meanR; meanT]
#define KSPLIT 32              // K-split factor for G = [R;T] * C^T
#define KSLICE (DDIM / KSPLIT) // 64
#define MARGIN 0.5f
#define FPSCALE 268435456.0    // 2^28 fixed-point scale for deterministic atomic sum

// ---------------- scratch (static device globals; no allocation) ----------------
__device__ float d_M[MROWS][DDIM];            // class means [R;T]          (2 MB)
__device__ float d_C[NCLS][DDIM];             // 0.5*(R+T)                  (1 MB)
__device__ float d_Gp[KSPLIT][MROWS * NCLS];  // GEMM K-split partials      (4 MB)
__device__ float d_n2[2][NCLS][4];            // per-chunk norm partials of means
__device__ int   d_cnt[NCLS];
__device__ int   d_off[NCLS];
__device__ short d_rows[NPTS];                // rows sorted by class (stable)
__device__ unsigned long long d_acc;          // fixed-point loss accumulator
__device__ int   d_done;

// =====================================================================
// Kernel 1: setup (1 block, 128 threads).
// Stable counting-sort of row indices by class -> d_rows/d_off/d_cnt.
// Deterministic: positions are ascending row index within each class.
// Also zeroes the loss accumulator for this graph replay.
// =====================================================================
__global__ void setup_kernel(const int* __restrict__ tgt) {
    __shared__ short          s_t[NPTS];          // 8 KB
    __shared__ unsigned short hist[128 * NCLS];   // [t][c], 32 KB
    __shared__ int            tot[NCLS];
    __shared__ int            scan[NCLS];

    const int tid = threadIdx.x;   // 128 threads
    if (tid == 0) { d_acc = 0ULL; d_done = 0; }

    for (int i = tid; i < NPTS; i += 128) s_t[i] = (short)tgt[i];
    for (int i = tid; i < (128 * NCLS) / 2; i += 128)
        ((unsigned int*)hist)[i] = 0u;
    __syncthreads();

    // Phase A: per-thread counts over its contiguous 32-row slice
    const int base = tid * 32;
    #pragma unroll 4
    for (int j = 0; j < 32; j++) {
        int c = s_t[base + j];
        hist[tid * NCLS + c]++;
    }
    __syncthreads();

    // Phase B: thread c: exclusive prefix across t (in place), total
    {
        int c = tid;
        int run = 0;
        for (int t = 0; t < 128; t++) {
            int v = hist[t * NCLS + c];
            hist[t * NCLS + c] = (unsigned short)run;
            run += v;
        }
        tot[c] = run;
    }
    __syncthreads();

    // class-offset scan (Hillis-Steele inclusive, then shift)
    scan[tid] = tot[tid];
    __syncthreads();
    #pragma unroll
    for (int off = 1; off < NCLS; off <<= 1) {
        int v = scan[tid];
        int add = (tid >= off) ? scan[tid - off] : 0;
        __syncthreads();
        scan[tid] = v + add;
        __syncthreads();
    }
    const int excl = scan[tid] - tot[tid];
    d_cnt[tid] = tot[tid];
    d_off[tid] = excl;
    __syncthreads();
    tot[tid] = excl;               // reuse as exclusive class offsets
    __syncthreads();

    // Phase C: stable scatter
    #pragma unroll 4
    for (int j = 0; j < 32; j++) {
        int c = s_t[base + j];
        int pos = tot[c] + hist[tid * NCLS + c];
        hist[tid * NCLS + c]++;
        d_rows[pos] = (short)(base + j);
    }
}

// =====================================================================
// Kernel 2: segment means + C + norm partials.
// grid (NCLS, 4 D-chunks of 512 cols), 128 threads (float4 per thread).
// Streams 64 MB of inputs exactly once -> DRAM-bound (~8 us floor).
// =====================================================================
__global__ void segmean_kernel(const float* __restrict__ m1,
                               const float* __restrict__ m2) {
    const int c     = blockIdx.x;
    const int chunk = blockIdx.y;
    const int tid   = threadIdx.x;

    __shared__ short s_rows[NPTS];   // 8 KB worst-case capacity
    const int cnt = d_cnt[c];
    const int off = d_off[c];
    for (int i = tid; i < cnt; i += 128) s_rows[i] = d_rows[off + i];
    __syncthreads();

    const int col = chunk * 512 + tid * 4;
    float4 aR = make_float4(0.f, 0.f, 0.f, 0.f);
    float4 aT = make_float4(0.f, 0.f, 0.f, 0.f);
    #pragma unroll 4
    for (int j = 0; j < cnt; j++) {
        size_t basep = (size_t)s_rows[j] * DDIM + col;
        float4 x = *(const float4*)(m1 + basep);
        float4 y = *(const float4*)(m2 + basep);
        aR.x += x.x; aR.y += x.y; aR.z += x.z; aR.w += x.w;
        aT.x += y.x; aT.y += y.y; aT.z += y.z; aT.w += y.w;
    }
    const float inv = 1.0f / fmaxf((float)cnt, 1.0f);
    aR.x *= inv; aR.y *= inv; aR.z *= inv; aR.w *= inv;
    aT.x *= inv; aT.y *= inv; aT.z *= inv; aT.w *= inv;

    *(float4*)&d_M[c][col]        = aR;
    *(float4*)&d_M[NCLS + c][col] = aT;
    float4 cc = make_float4(0.5f * (aR.x + aT.x), 0.5f * (aR.y + aT.y),
                            0.5f * (aR.z + aT.z), 0.5f * (aR.w + aT.w));
    *(float4*)&d_C[c][col] = cc;

    // norm partials of the means for this chunk
    float nR = aR.x * aR.x + aR.y * aR.y + aR.z * aR.z + aR.w * aR.w;
    float nT = aT.x * aT.x + aT.y * aT.y + aT.z * aT.z + aT.w * aT.w;
    #pragma unroll
    for (int o = 16; o > 0; o >>= 1) {
        nR += __shfl_down_sync(0xffffffffu, nR, o);
        nT += __shfl_down_sync(0xffffffffu, nT, o);
    }
    __shared__ float wr[4], wt[4];
    const int wid = tid >> 5, lane = tid & 31;
    if (lane == 0) { wr[wid] = nR; wt[wid] = nT; }
    __syncthreads();
    if (tid == 0) {
        d_n2[0][c][chunk] = wr[0] + wr[1] + wr[2] + wr[3];
        d_n2[1][c][chunk] = wt[0] + wt[1] + wt[2] + wt[3];
    }
}

// =====================================================================
// Kernel 3: Gp[z] = [R;T][:, zK:(z+1)K] * C[:, zK:(z+1)K]^T
// grid (4 row-tiles, 2 col-tiles, KSPLIT), 256 threads, 64x64 tile,
// 4x4 register micro-tile, K-major smem (conflict-free float4 LDS).
// =====================================================================
__global__ void gemm_kernel() {
    const int tid = threadIdx.x;
    const int tx = tid & 15, ty = tid >> 4;
    const int row0 = blockIdx.x * 64;       // into d_M (0..192)
    const int col0 = blockIdx.y * 64;       // into d_C (0 or 64)
    const int kb   = blockIdx.z * KSLICE;   // 64-wide K slice

    __shared__ float As[KSLICE][64];   // [k][row], 16 KB
    __shared__ float Bs[KSLICE][64];   // [k][col], 16 KB

    float acc[4][4];
    #pragma unroll
    for (int i = 0; i < 4; i++)
        #pragma unroll
        for (int j = 0; j < 4; j++) acc[i][j] = 0.f;

    // cooperative transposed load (r varies over lanes -> conflict-free STS)
    #pragma unroll
    for (int it = 0; it < 4; it++) {
        int t = tid + it * 256;     // 0..1023
        int r = t & 63;
        int q = t >> 6;             // float4 index in k (0..15)
        float4 a = *(const float4*)&d_M[row0 + r][kb + q * 4];
        As[q * 4 + 0][r] = a.x; As[q * 4 + 1][r] = a.y;
        As[q * 4 + 2][r] = a.z; As[q * 4 + 3][r] = a.w;
        float4 b = *(const float4*)&d_C[col0 + r][kb + q * 4];
        Bs[q * 4 + 0][r] = b.x; Bs[q * 4 + 1][r] = b.y;
        Bs[q * 4 + 2][r] = b.z; Bs[q * 4 + 3][r] = b.w;
    }
    __syncthreads();

    #pragma unroll 16
    for (int k = 0; k < KSLICE; k++) {
        float4 av = *(const float4*)&As[k][ty * 4];
        float4 bv = *(const float4*)&Bs[k][tx * 4];
        acc[0][0] += av.x * bv.x; acc[0][1] += av.x * bv.y;
        acc[0][2] += av.x * bv.z; acc[0][3] += av.x * bv.w;
        acc[1][0] += av.y * bv.x; acc[1][1] += av.y * bv.y;
        acc[1][2] += av.y * bv.z; acc[1][3] += av.y * bv.w;
        acc[2][0] += av.z * bv.x; acc[2][1] += av.z * bv.y;
        acc[2][2] += av.z * bv.z; acc[2][3] += av.z * bv.w;
        acc[3][0] += av.w * bv.x; acc[3][1] += av.w * bv.y;
        acc[3][2] += av.w * bv.z; acc[3][3] += av.w * bv.w;
    }

    float* out = d_Gp[blockIdx.z];
    #pragma unroll
    for (int i = 0; i < 4; i++)
        #pragma unroll
        for (int j = 0; j < 4; j++)
            out[(row0 + ty * 4 + i) * NCLS + (col0 + tx * 4 + j)] = acc[i][j];
}

// =====================================================================
// Kernel 4: fused K-split reduction + class-pair loss.
// grid 64 blocks x 256 threads (one thread per class pair).
// Deterministic cross-block reduction: fixed-point integer atomicAdd
// (order-independent) + last-block-writes-out.
// =====================================================================
__global__ void loss_kernel(float* __restrict__ out) {
    const int tid = threadIdx.x;
    __shared__ float s_cb2[NCLS];

    // center norms from G diagonal: cb2[b] = 0.5*(G[b][b] + G[128+b][b])
    if (tid < NCLS) {
        int b = tid;
        float s1 = 0.f, s2 = 0.f;
        #pragma unroll
        for (int z = 0; z < KSPLIT; z++) {
            s1 += d_Gp[z][b * NCLS + b];
            s2 += d_Gp[z][(NCLS + b) * NCLS + b];
        }
        s_cb2[b] = 0.5f * (s1 + s2);
    }
    __syncthreads();

    const int p = blockIdx.x * 256 + tid;   // 0..16383
    const int a = p >> 7, b = p & (NCLS - 1);

    float g1 = 0.f, g2 = 0.f;
    #pragma unroll
    for (int z = 0; z < KSPLIT; z++) {
        g1 += d_Gp[z][a * NCLS + b];
        g2 += d_Gp[z][(NCLS + a) * NCLS + b];
    }
    float ra2 = d_n2[0][a][0] + d_n2[0][a][1] + d_n2[0][a][2] + d_n2[0][a][3];
    float ta2 = d_n2[1][a][0] + d_n2[1][a][1] + d_n2[1][a][2] + d_n2[1][a][3];

    float sq1 = fmaxf(ra2 + s_cb2[b] - 2.f * g1, 1e-12f);
    float sq2 = fmaxf(ta2 + s_cb2[b] - 2.f * g2, 1e-12f);
    float term;
    if (a == b) {
        term = sq1 + sq2;                         // label=1: dist^2
    } else {
        float dd1 = sqrtf(sqrtf(sq1) + 1e-10f);   // sqrt of sqrt
        float dd2 = sqrtf(sqrtf(sq2) + 1e-10f);
        float h1 = fmaxf(MARGIN - dd1, 0.f);
        float h2 = fmaxf(MARGIN - dd2, 0.f);
        term = h1 * h1 + h2 * h2;
    }
    double contrib = (double)((float)(d_cnt[a] * d_cnt[b])) * (double)term;

    __shared__ double sred[256];
    sred[tid] = contrib;
    __syncthreads();
    #pragma unroll
    for (int s = 128; s > 0; s >>= 1) {
        if (tid < s) sred[tid] += sred[tid + s];
        __syncthreads();
    }

    if (tid == 0) {
        unsigned long long q = (unsigned long long)(sred[0] * FPSCALE + 0.5);
        atomicAdd(&d_acc, q);
        __threadfence();
        if (atomicAdd(&d_done, 1) == gridDim.x - 1) {
            unsigned long long tot = atomicAdd(&d_acc, 0ULL);
            out[0] = (float)(((double)tot / FPSCALE) /
                             ((double)NPTS * (double)NPTS));
        }
    }
}

// =====================================================================
// kernel_launch: graph-capturable, allocation-free pipeline (4 kernels).
// inputs: [0] modal1 (N*D f32), [1] modal2 (N*D f32), [2] targets (N i32)
// output: scalar f32
// =====================================================================
extern "C" void kernel_launch(void* const* d_in, const int* in_sizes, int n_in,
                              void* d_out, int out_size) {
    (void)in_sizes; (void)n_in; (void)out_size;
    const float* m1  = (const float*)d_in[0];
    const float* m2  = (const float*)d_in[1];
    const int*   tgt = (const int*)d_in[2];
    float* out = (float*)d_out;

    setup_kernel<<<1, 128>>>(tgt);
    segmean_kernel<<<dim3(NCLS, 4), 128>>>(m1, m2);
    gemm_kernel<<<dim3(4, 2, KSPLIT), 256>>>();
    loss_kernel<<<64, 256>>>(out);
}

// round 4
// speedup vs baseline: 1.5651x; 1.0059x over previous
#include <cuda_runtime.h>
#include <math.h>

// Problem constants
#define NPTS 4096
#define DDIM 2048
#define NCLS 128
#define MROWS 256              // stacked [meanR; meanT]
#define KSPLIT 32              // K-split factor for G = [R;T] * C^T
#define KSLICE (DDIM / KSPLIT) // 64
#define MARGIN 0.5f
#define FPSCALE 268435456.0    // 2^28 for the final scalar accumulator
#define GSCALE  4294967296.0   // 2^32 fixed-point scale for G accumulation
#define GINV    (1.0 / 4294967296.0)

// ---------------- scratch (static device globals; no allocation) ----------------
__device__ float d_M[MROWS][DDIM];            // class means [R;T]   (2 MB)
__device__ float d_C[NCLS][DDIM];             // 0.5*(R+T)           (1 MB)
__device__ long long d_Gq[MROWS * NCLS];      // fixed-point G       (256 KB)
__device__ float d_n2[2][NCLS][4];            // per-chunk mean-norm partials
__device__ int   d_cnt[NCLS];
__device__ int   d_off[NCLS];
__device__ short d_rows[NPTS];                // rows sorted by class (stable)
__device__ unsigned long long d_acc;          // fixed-point loss accumulator
__device__ int   d_done;

// =====================================================================
// Kernel 1: setup. grid 9 blocks x 128 threads.
// Block 0: stable counting-sort of rows by class (deterministic) and
//          zeroing of scalar accumulators.
// Blocks 1..8: zero the fixed-point G accumulator (256 KB).
// =====================================================================
__global__ void setup_kernel(const int* __restrict__ tgt) {
    const int tid = threadIdx.x;   // 128 threads

    if (blockIdx.x != 0) {
        // zero 32768 u64 / 8 blocks = 4096 per block
        long long* g = d_Gq + (blockIdx.x - 1) * 4096;
        #pragma unroll
        for (int i = 0; i < 32; i++) g[tid + i * 128] = 0LL;
        return;
    }

    __shared__ short          s_t[NPTS];          // 8 KB
    __shared__ unsigned short hist[128 * NCLS];   // [t][c], 32 KB
    __shared__ int            tot[NCLS];
    __shared__ int            scan[NCLS];

    if (tid == 0) { d_acc = 0ULL; d_done = 0; }

    for (int i = tid; i < NPTS; i += 128) s_t[i] = (short)tgt[i];
    for (int i = tid; i < (128 * NCLS) / 2; i += 128)
        ((unsigned int*)hist)[i] = 0u;
    __syncthreads();

    // Phase A: per-thread counts over its contiguous 32-row slice
    const int base = tid * 32;
    #pragma unroll 4
    for (int j = 0; j < 32; j++) {
        int c = s_t[base + j];
        hist[tid * NCLS + c]++;
    }
    __syncthreads();

    // Phase B: thread c: exclusive prefix across t (in place), total
    {
        int c = tid;
        int run = 0;
        for (int t = 0; t < 128; t++) {
            int v = hist[t * NCLS + c];
            hist[t * NCLS + c] = (unsigned short)run;
            run += v;
        }
        tot[c] = run;
    }
    __syncthreads();

    // class-offset scan (Hillis-Steele inclusive, then shift)
    scan[tid] = tot[tid];
    __syncthreads();
    #pragma unroll
    for (int off = 1; off < NCLS; off <<= 1) {
        int v = scan[tid];
        int add = (tid >= off) ? scan[tid - off] : 0;
        __syncthreads();
        scan[tid] = v + add;
        __syncthreads();
    }
    const int excl = scan[tid] - tot[tid];
    d_cnt[tid] = tot[tid];
    d_off[tid] = excl;
    __syncthreads();
    tot[tid] = excl;               // reuse as exclusive class offsets
    __syncthreads();

    // Phase C: stable scatter
    #pragma unroll 4
    for (int j = 0; j < 32; j++) {
        int c = s_t[base + j];
        int pos = tot[c] + hist[tid * NCLS + c];
        hist[tid * NCLS + c]++;
        d_rows[pos] = (short)(base + j);
    }
}

// =====================================================================
// Kernel 2: segment means + C + mean-norm partials.
// grid (NCLS, 4 D-chunks of 512 cols), 128 threads (float4 per thread).
// Streams 64 MB of inputs exactly once -> DRAM-bound (~8 us floor).
// =====================================================================
__global__ void segmean_kernel(const float* __restrict__ m1,
                               const float* __restrict__ m2) {
    const int c     = blockIdx.x;
    const int chunk = blockIdx.y;
    const int tid   = threadIdx.x;

    __shared__ short s_rows[NPTS];   // worst-case capacity
    const int cnt = d_cnt[c];
    const int off = d_off[c];
    for (int i = tid; i < cnt; i += 128) s_rows[i] = d_rows[off + i];
    __syncthreads();

    const int col = chunk * 512 + tid * 4;
    float4 aR = make_float4(0.f, 0.f, 0.f, 0.f);
    float4 aT = make_float4(0.f, 0.f, 0.f, 0.f);
    #pragma unroll 4
    for (int j = 0; j < cnt; j++) {
        size_t basep = (size_t)s_rows[j] * DDIM + col;
        float4 x = *(const float4*)(m1 + basep);
        float4 y = *(const float4*)(m2 + basep);
        aR.x += x.x; aR.y += x.y; aR.z += x.z; aR.w += x.w;
        aT.x += y.x; aT.y += y.y; aT.z += y.z; aT.w += y.w;
    }
    const float inv = 1.0f / fmaxf((float)cnt, 1.0f);
    aR.x *= inv; aR.y *= inv; aR.z *= inv; aR.w *= inv;
    aT.x *= inv; aT.y *= inv; aT.z *= inv; aT.w *= inv;

    *(float4*)&d_M[c][col]        = aR;
    *(float4*)&d_M[NCLS + c][col] = aT;
    float4 cc = make_float4(0.5f * (aR.x + aT.x), 0.5f * (aR.y + aT.y),
                            0.5f * (aR.z + aT.z), 0.5f * (aR.w + aT.w));
    *(float4*)&d_C[c][col] = cc;

    // norm partials of the means for this chunk
    float nR = aR.x * aR.x + aR.y * aR.y + aR.z * aR.z + aR.w * aR.w;
    float nT = aT.x * aT.x + aT.y * aT.y + aT.z * aT.z + aT.w * aT.w;
    #pragma unroll
    for (int o = 16; o > 0; o >>= 1) {
        nR += __shfl_down_sync(0xffffffffu, nR, o);
        nT += __shfl_down_sync(0xffffffffu, nT, o);
    }
    __shared__ float wr[4], wt[4];
    const int wid = tid >> 5, lane = tid & 31;
    if (lane == 0) { wr[wid] = nR; wt[wid] = nT; }
    __syncthreads();
    if (tid == 0) {
        d_n2[0][c][chunk] = wr[0] + wr[1] + wr[2] + wr[3];
        d_n2[1][c][chunk] = wt[0] + wt[1] + wt[2] + wt[3];
    }
}

// =====================================================================
// Kernel 3: G += [R;T][:, z*64:(z+1)*64] * C[:, z*64:(z+1)*64]^T
// grid (4 row-tiles, 2 col-tiles, KSPLIT), 256 threads, 64x64 tile,
// 4x4 register micro-tile, K-major smem (conflict-free float4 LDS).
// K-split reduction via fixed-point int64 atomics: order-independent
// integer adds -> deterministic, no partials buffer, no reduce kernel.
// =====================================================================
__global__ void gemm_kernel() {
    const int tid = threadIdx.x;
    const int tx = tid & 15, ty = tid >> 4;
    const int row0 = blockIdx.x * 64;       // into d_M (0..192)
    const int col0 = blockIdx.y * 64;       // into d_C (0 or 64)
    const int kb   = blockIdx.z * KSLICE;   // 64-wide K slice

    __shared__ float As[KSLICE][64];   // [k][row], 16 KB
    __shared__ float Bs[KSLICE][64];   // [k][col], 16 KB

    float acc[4][4];
    #pragma unroll
    for (int i = 0; i < 4; i++)
        #pragma unroll
        for (int j = 0; j < 4; j++) acc[i][j] = 0.f;

    // cooperative transposed load (r varies over lanes -> conflict-free STS)
    #pragma unroll
    for (int it = 0; it < 4; it++) {
        int t = tid + it * 256;     // 0..1023
        int r = t & 63;
        int q = t >> 6;             // float4 index in k (0..15)
        float4 a = *(const float4*)&d_M[row0 + r][kb + q * 4];
        As[q * 4 + 0][r] = a.x; As[q * 4 + 1][r] = a.y;
        As[q * 4 + 2][r] = a.z; As[q * 4 + 3][r] = a.w;
        float4 b = *(const float4*)&d_C[col0 + r][kb + q * 4];
        Bs[q * 4 + 0][r] = b.x; Bs[q * 4 + 1][r] = b.y;
        Bs[q * 4 + 2][r] = b.z; Bs[q * 4 + 3][r] = b.w;
    }
    __syncthreads();

    #pragma unroll 16
    for (int k = 0; k < KSLICE; k++) {
        float4 av = *(const float4*)&As[k][ty * 4];
        float4 bv = *(const float4*)&Bs[k][tx * 4];
        acc[0][0] += av.x * bv.x; acc[0][1] += av.x * bv.y;
        acc[0][2] += av.x * bv.z; acc[0][3] += av.x * bv.w;
        acc[1][0] += av.y * bv.x; acc[1][1] += av.y * bv.y;
        acc[1][2] += av.y * bv.z; acc[1][3] += av.y * bv.w;
        acc[2][0] += av.z * bv.x; acc[2][1] += av.z * bv.y;
        acc[2][2] += av.z * bv.z; acc[2][3] += av.z * bv.w;
        acc[3][0] += av.w * bv.x; acc[3][1] += av.w * bv.y;
        acc[3][2] += av.w * bv.z; acc[3][3] += av.w * bv.w;
    }

    #pragma unroll
    for (int i = 0; i < 4; i++)
        #pragma unroll
        for (int j = 0; j < 4; j++) {
            long long q = __double2ll_rn((double)acc[i][j] * GSCALE);
            atomicAdd((unsigned long long*)
                          &d_Gq[(row0 + ty * 4 + i) * NCLS + (col0 + tx * 4 + j)],
                      (unsigned long long)q);
        }
}

// =====================================================================
// Kernel 4: class-pair loss. grid 64 x 256 (one thread per class pair).
// Reads the 256 KB L2-resident fixed-point G. Deterministic cross-block
// reduction via fixed-point atomic + last-block-writes-out.
// =====================================================================
__global__ void loss_kernel(float* __restrict__ out) {
    const int tid = threadIdx.x;
    __shared__ float s_cb2[NCLS];

    // center norms from G diagonal: cb2[b] = 0.5*(G[b][b] + G[128+b][b])
    if (tid < NCLS) {
        int b = tid;
        double s1 = (double)d_Gq[b * NCLS + b] * GINV;
        double s2 = (double)d_Gq[(NCLS + b) * NCLS + b] * GINV;
        s_cb2[b] = (float)(0.5 * (s1 + s2));
    }
    __syncthreads();

    const int p = blockIdx.x * 256 + tid;   // 0..16383
    const int a = p >> 7, b = p & (NCLS - 1);

    float g1 = (float)((double)d_Gq[a * NCLS + b] * GINV);
    float g2 = (float)((double)d_Gq[(NCLS + a) * NCLS + b] * GINV);

    float ra2 = d_n2[0][a][0] + d_n2[0][a][1] + d_n2[0][a][2] + d_n2[0][a][3];
    float ta2 = d_n2[1][a][0] + d_n2[1][a][1] + d_n2[1][a][2] + d_n2[1][a][3];

    float sq1 = fmaxf(ra2 + s_cb2[b] - 2.f * g1, 1e-12f);
    float sq2 = fmaxf(ta2 + s_cb2[b] - 2.f * g2, 1e-12f);
    float term;
    if (a == b) {
        term = sq1 + sq2;                         // label=1: dist^2
    } else {
        float dd1 = sqrtf(sqrtf(sq1) + 1e-10f);   // sqrt of sqrt
        float dd2 = sqrtf(sqrtf(sq2) + 1e-10f);
        float h1 = fmaxf(MARGIN - dd1, 0.f);
        float h2 = fmaxf(MARGIN - dd2, 0.f);
        term = h1 * h1 + h2 * h2;
    }
    double contrib = (double)((float)(d_cnt[a] * d_cnt[b])) * (double)term;

    __shared__ double sred[256];
    sred[tid] = contrib;
    __syncthreads();
    #pragma unroll
    for (int s = 128; s > 0; s >>= 1) {
        if (tid < s) sred[tid] += sred[tid + s];
        __syncthreads();
    }

    if (tid == 0) {
        unsigned long long q = (unsigned long long)(sred[0] * FPSCALE + 0.5);
        atomicAdd(&d_acc, q);
        __threadfence();
        if (atomicAdd(&d_done, 1) == gridDim.x - 1) {
            unsigned long long tot = atomicAdd(&d_acc, 0ULL);
            out[0] = (float)(((double)tot / FPSCALE) /
                             ((double)NPTS * (double)NPTS));
        }
    }
}

// =====================================================================
// kernel_launch: graph-capturable, allocation-free pipeline (4 kernels).
// inputs: [0] modal1 (N*D f32), [1] modal2 (N*D f32), [2] targets (N i32)
// output: scalar f32
// =====================================================================
extern "C" void kernel_launch(void* const* d_in, const int* in_sizes, int n_in,
                              void* d_out, int out_size) {
    (void)in_sizes; (void)n_in; (void)out_size;
    const float* m1  = (const float*)d_in[0];
    const float* m2  = (const float*)d_in[1];
    const int*   tgt = (const int*)d_in[2];
    float* out = (float*)d_out;

    setup_kernel<<<9, 128>>>(tgt);
    segmean_kernel<<<dim3(NCLS, 4), 128>>>(m1, m2);
    gemm_kernel<<<dim3(4, 2, KSPLIT), 256>>>();
    loss_kernel<<<64, 256>>>(out);
}